// round 17
// baseline (speedup 1.0000x reference)
#include <cuda_runtime.h>
#include <cuda_fp16.h>
#include <cstdint>

#define N_NODES 100000
#define N_EDGES 1600000
#define C 32

// Scratch (device globals; zero-initialized at module load).
// g_degi is consumed and re-zeroed by k_gemm each call -> replay-safe.
// g_acc is fully overwritten by k_gemm (self-loop init) each call.
__device__ int   g_degi[N_NODES];
__device__ float g_dinv[N_NODES];
__device__ uint4 g_hs[N_NODES * 4];    // fp16 messages: 32ch x 2B = 64B/row
__device__ uint4 g_acc[N_NODES * 4];   // fp16 accumulators, same layout

// ---------------------------------------------------------------------------
// K1: in-degree histogram over targets, 1 edge/thread (proven ~12.7us).
__global__ void k_count(const int* __restrict__ col) {
    int e = blockIdx.x * blockDim.x + threadIdx.x;
    if (e < N_EDGES) atomicAdd(&g_degi[__ldg(col + e)], 1);
}

// K2: dinv = rsqrt(deg+1); hs(fp16) = (x @ W^T) * dinv; acc = hs (self-loop
//     init, fully overwrites g_acc). Re-zeroes g_degi for the next replay.
//     Block = 8 nodes x 32 channels.
__global__ void k_gemm(const float* __restrict__ x,
                       const float* __restrict__ W) {
    __shared__ float Wsh[C][C + 1];   // Wsh[k][co] = W[co*C + k]
    int tid = threadIdx.x;
    #pragma unroll
    for (int i = tid; i < C * C; i += 256) {
        Wsh[i % C][i / C] = W[i];
    }
    __syncthreads();

    int n  = blockIdx.x * 8 + (tid >> 5);
    int co = tid & 31;
    if (n >= N_NODES) return;

    int deg = g_degi[n];
    if (co == 0) g_degi[n] = 0;                    // reset for next replay
    float dinv = rsqrtf((float)(deg + 1));         // +1 = self loop
    if (co == 0) g_dinv[n] = dinv;

    const float* xr = x + n * C;
    float acc = 0.0f;
    #pragma unroll
    for (int k = 0; k < C; k++) acc += __ldg(xr + k) * Wsh[k][co];

    __half hs = __float2half(acc * dinv);
    reinterpret_cast<__half*>(g_hs)[n * C + co]  = hs;   // message
    reinterpret_cast<__half*>(g_acc)[n * C + co] = hs;   // self-loop init
}

// K3: fp16 vector RED scatter — acc[col] += hs[row], 4 lanes per edge,
//     each lane one red.global.add.noftz.v4.f16x2 (16B = 8 halves).
//     Half the REDG lanes of the f32 scatter; no binning kernel needed.
__global__ void k_scatter(const int* __restrict__ rowv,
                          const int* __restrict__ colv) {
    int t = blockIdx.x * blockDim.x + threadIdx.x;
    int e = t >> 2;
    int g = t & 3;
    if (e >= N_EDGES) return;

    int r = __ldg(rowv + e);
    int c = __ldg(colv + e);
    uint4 v = g_hs[r * 4 + g];            // 16B coalesced (64B per group)
    uint4* dst = &g_acc[c * 4 + g];
    asm volatile("red.global.add.noftz.v4.f16x2 [%0], {%1, %2, %3, %4};"
                 :: "l"(dst), "r"(v.x), "r"(v.y), "r"(v.z), "r"(v.w)
                 : "memory");
}

// K4: out(f32) = f32(acc) * dinv[node] + b[channel].
//     Thread per uint4 = 8 channels.
__global__ void k_final(float4* __restrict__ out, const float* __restrict__ b) {
    int i = blockIdx.x * blockDim.x + threadIdx.x;
    if (i >= N_NODES * 4) return;
    int n = i >> 2;
    int g = i & 3;

    uint4 w = g_acc[i];
    float2 f0 = __half22float2(*reinterpret_cast<__half2*>(&w.x));
    float2 f1 = __half22float2(*reinterpret_cast<__half2*>(&w.y));
    float2 f2 = __half22float2(*reinterpret_cast<__half2*>(&w.z));
    float2 f3 = __half22float2(*reinterpret_cast<__half2*>(&w.w));

    float d = g_dinv[n];
    const float4* b4 = reinterpret_cast<const float4*>(b);
    float4 bb0 = __ldg(b4 + 2 * g);
    float4 bb1 = __ldg(b4 + 2 * g + 1);

    float4 o0, o1;
    o0.x = fmaf(f0.x, d, bb0.x);
    o0.y = fmaf(f0.y, d, bb0.y);
    o0.z = fmaf(f1.x, d, bb0.z);
    o0.w = fmaf(f1.y, d, bb0.w);
    o1.x = fmaf(f2.x, d, bb1.x);
    o1.y = fmaf(f2.y, d, bb1.y);
    o1.z = fmaf(f3.x, d, bb1.z);
    o1.w = fmaf(f3.y, d, bb1.w);
    out[i * 2]     = o0;
    out[i * 2 + 1] = o1;
}

// ---------------------------------------------------------------------------
extern "C" void kernel_launch(void* const* d_in, const int* in_sizes, int n_in,
                              void* d_out, int out_size) {
    const float* x  = (const float*)d_in[0];
    const int*   ei = (const int*)d_in[1];    // [2, E]: row then col
    const float* W  = (const float*)d_in[2];
    const float* b  = (const float*)d_in[3];
    float4* out = (float4*)d_out;

    const int* rowv = ei;
    const int* colv = ei + N_EDGES;

    k_count<<<(N_EDGES + 255) / 256, 256>>>(colv);
    k_gemm<<<(N_NODES + 7) / 8, 256>>>(x, W);
    k_scatter<<<(N_EDGES * 4 + 255) / 256, 256>>>(rowv, colv);
    k_final<<<(N_NODES * 4 + 255) / 256, 256>>>(out, b);
}